// round 7
// baseline (speedup 1.0000x reference)
#include <cuda_runtime.h>
#include <math.h>
#include <stdint.h>

#define DIMS   768
#define HEADS  8
#define HD     96
#define SEQL   2048
#define BATCH  2
#define NROWS  (BATCH*SEQL)   // 4096

// ---------------------------------------------------------------------------
// Scratch (static device globals: allocation-free, graph-capture safe)
// ---------------------------------------------------------------------------
__device__ float    g_q  [NROWS*DIMS];
__device__ float    g_k  [NROWS*DIMS];
__device__ float    g_v  [NROWS*DIMS];
__device__ float    g_att[NROWS*DIMS];
__device__ uint32_t g_vt [BATCH*HEADS*HD*SEQL];   // V^T, tf32 bits
// tf32-rounded copies of inputs/weights (cvt-free GEMM fragments)
__device__ float    g_qin[NROWS*DIMS];
__device__ float    g_kin[NROWS*DIMS];
__device__ float    g_vin[NROWS*DIMS];
__device__ float    g_wq [DIMS*DIMS];
__device__ float    g_wk [DIMS*DIMS];
__device__ float    g_wv [DIMS*DIMS];
__device__ float    g_wo [DIMS*DIMS];

// ---------------------------------------------------------------------------
// PTX helpers
// ---------------------------------------------------------------------------
__device__ __forceinline__ uint32_t smem_u32(const void* p) {
    uint32_t a;
    asm("{ .reg .u64 t; cvta.to.shared.u64 t, %1; cvt.u32.u64 %0, t; }" : "=r"(a) : "l"(p));
    return a;
}
__device__ __forceinline__ void cp_async16(uint32_t dst, const void* src) {
    asm volatile("cp.async.cg.shared.global [%0], [%1], 16;" :: "r"(dst), "l"(src));
}
__device__ __forceinline__ void cp_async_commit() { asm volatile("cp.async.commit_group;" ::: "memory"); }
template<int N>
__device__ __forceinline__ void cp_async_wait() { asm volatile("cp.async.wait_group %0;" :: "n"(N) : "memory"); }

__device__ __forceinline__ uint32_t f2tf32(float x) {
    uint32_t u;
    asm("cvt.rna.tf32.f32 %0, %1;" : "=r"(u) : "f"(x));
    return u;
}
__device__ __forceinline__ void mma_tf32(float& c0, float& c1, float& c2, float& c3,
                                         uint32_t a0, uint32_t a1, uint32_t a2, uint32_t a3,
                                         uint32_t b0, uint32_t b1) {
    asm volatile(
        "mma.sync.aligned.m16n8k8.row.col.f32.tf32.tf32.f32 "
        "{%0,%1,%2,%3}, {%4,%5,%6,%7}, {%8,%9}, {%0,%1,%2,%3};"
        : "+f"(c0), "+f"(c1), "+f"(c2), "+f"(c3)
        : "r"(a0), "r"(a1), "r"(a2), "r"(a3), "r"(b0), "r"(b1));
}

// ---------------------------------------------------------------------------
// tf32 pre-rounding passes (float4 vectorized)
// ---------------------------------------------------------------------------
__device__ __forceinline__ float4 round4(float4 x) {
    return make_float4(__uint_as_float(f2tf32(x.x)), __uint_as_float(f2tf32(x.y)),
                       __uint_as_float(f2tf32(x.z)), __uint_as_float(f2tf32(x.w)));
}
// inputs: 3 matrices [NROWS*DIMS], blockIdx.y selects
__global__ __launch_bounds__(256)
void round_inputs_kernel(const float* __restrict__ a, const float* __restrict__ b,
                         const float* __restrict__ c, float* __restrict__ oa,
                         float* __restrict__ ob, float* __restrict__ oc)
{
    const float* src; float* dst;
    if      (blockIdx.y == 0) { src = a; dst = oa; }
    else if (blockIdx.y == 1) { src = b; dst = ob; }
    else                      { src = c; dst = oc; }
    int i = blockIdx.x * 256 + threadIdx.x;            // float4 index
    ((float4*)dst)[i] = round4(((const float4*)src)[i]);
}
// weights: 4 matrices [DIMS*DIMS]
__global__ __launch_bounds__(256)
void round_weights_kernel(const float* __restrict__ a, const float* __restrict__ b,
                          const float* __restrict__ c, const float* __restrict__ d,
                          float* __restrict__ oa, float* __restrict__ ob,
                          float* __restrict__ oc, float* __restrict__ od)
{
    const float* src; float* dst;
    if      (blockIdx.y == 0) { src = a; dst = oa; }
    else if (blockIdx.y == 1) { src = b; dst = ob; }
    else if (blockIdx.y == 2) { src = c; dst = oc; }
    else                      { src = d; dst = od; }
    int i = blockIdx.x * 256 + threadIdx.x;
    ((float4*)dst)[i] = round4(((const float4*)src)[i]);
}

// ---------------------------------------------------------------------------
// NT GEMM via mma.sync tf32; operands PRE-ROUNDED to tf32 bits (no cvt in loop)
// ---------------------------------------------------------------------------
#define TM   128
#define TN   128
#define KCH  32
#define PITCH 36
#define STAGE_F (TM * PITCH)
#define GEMM_SMEM_BYTES (4 * STAGE_F * 4)   // 73728 B

__device__ __forceinline__
void gemm_body(const float* __restrict__ A, const float* __restrict__ B,
               float* __restrict__ C, int M, int N, int K, float* smem)
{
    float* sA = smem;
    float* sB = smem + 2 * STAGE_F;

    const int tid  = threadIdx.x;
    const int wid  = tid >> 5;
    const int lane = tid & 31;
    const int grp  = lane >> 2;
    const int thr  = lane & 3;
    const int wm   = (wid & 3) * 32;
    const int wn   = (wid >> 2) * 64;
    const int rowBase = blockIdx.x * TM;
    const int colBase = blockIdx.y * TN;

    const uint32_t sA_u = smem_u32(sA);
    const uint32_t sB_u = smem_u32(sB);

    float acc[2][8][4];
#pragma unroll
    for (int mt = 0; mt < 2; mt++)
#pragma unroll
        for (int nt = 0; nt < 8; nt++)
#pragma unroll
            for (int i = 0; i < 4; i++) acc[mt][nt][i] = 0.f;

    const int nChunks = K / KCH;

#define PREFETCH(ch)                                                            \
    do {                                                                        \
        int _k0 = (ch) * KCH;                                                   \
        uint32_t _dA = sA_u + ((ch) & 1) * STAGE_F * 4;                         \
        uint32_t _dB = sB_u + ((ch) & 1) * STAGE_F * 4;                         \
        _Pragma("unroll")                                                       \
        for (int _it = 0; _it < 4; _it++) {                                     \
            int _idx = tid + _it * 256;                                         \
            int _r = _idx >> 3, _seg = _idx & 7;                                \
            cp_async16(_dA + (_r * PITCH + _seg * 4) * 4,                       \
                       A + (size_t)(rowBase + _r) * K + _k0 + _seg * 4);        \
            cp_async16(_dB + (_r * PITCH + _seg * 4) * 4,                       \
                       B + (size_t)(colBase + _r) * K + _k0 + _seg * 4);        \
        }                                                                       \
        cp_async_commit();                                                      \
    } while (0)

    PREFETCH(0);

    for (int ch = 0; ch < nChunks; ch++) {
        if (ch + 1 < nChunks) { PREFETCH(ch + 1); cp_async_wait<1>(); }
        else                  { cp_async_wait<0>(); }
        __syncthreads();

        const float* cA = sA + (ch & 1) * STAGE_F;
        const float* cB = sB + (ch & 1) * STAGE_F;

#pragma unroll
        for (int ks = 0; ks < 4; ks++) {
            const int kk = ks * 8;
            uint32_t af[2][4];
#pragma unroll
            for (int mt = 0; mt < 2; mt++) {
                int rb = wm + mt * 16 + grp;
                af[mt][0] = __float_as_uint(cA[(rb    ) * PITCH + kk + thr    ]);
                af[mt][1] = __float_as_uint(cA[(rb + 8) * PITCH + kk + thr    ]);
                af[mt][2] = __float_as_uint(cA[(rb    ) * PITCH + kk + thr + 4]);
                af[mt][3] = __float_as_uint(cA[(rb + 8) * PITCH + kk + thr + 4]);
            }
            uint32_t bf[8][2];
#pragma unroll
            for (int nt = 0; nt < 8; nt++) {
                int cb = wn + nt * 8 + grp;
                bf[nt][0] = __float_as_uint(cB[cb * PITCH + kk + thr    ]);
                bf[nt][1] = __float_as_uint(cB[cb * PITCH + kk + thr + 4]);
            }
#pragma unroll
            for (int mt = 0; mt < 2; mt++)
#pragma unroll
                for (int nt = 0; nt < 8; nt++)
                    mma_tf32(acc[mt][nt][0], acc[mt][nt][1],
                             acc[mt][nt][2], acc[mt][nt][3],
                             af[mt][0], af[mt][1], af[mt][2], af[mt][3],
                             bf[nt][0], bf[nt][1]);
        }
        __syncthreads();
    }
#undef PREFETCH

#pragma unroll
    for (int mt = 0; mt < 2; mt++) {
        int r0 = rowBase + wm + mt * 16 + grp;
#pragma unroll
        for (int nt = 0; nt < 8; nt++) {
            int c0 = colBase + wn + nt * 8 + thr * 2;
            float2* p0 = (float2*)(C + (size_t)r0 * N + c0);
            float2* p1 = (float2*)(C + (size_t)(r0 + 8) * N + c0);
            *p0 = make_float2(acc[mt][nt][0], acc[mt][nt][1]);
            *p1 = make_float2(acc[mt][nt][2], acc[mt][nt][3]);
        }
    }
}

__global__ __launch_bounds__(256)
void gemm_qkv_kernel(const float* __restrict__ Qin, const float* __restrict__ Kin,
                     const float* __restrict__ Vin, const float* __restrict__ Wq,
                     const float* __restrict__ Wk, const float* __restrict__ Wv,
                     float* __restrict__ q, float* __restrict__ k, float* __restrict__ v)
{
    extern __shared__ float smem[];
    const float *A, *B;
    float* C;
    if      (blockIdx.z == 0) { A = Qin; B = Wq; C = q; }
    else if (blockIdx.z == 1) { A = Kin; B = Wk; C = k; }
    else                      { A = Vin; B = Wv; C = v; }
    gemm_body(A, B, C, NROWS, DIMS, DIMS, smem);
}

__global__ __launch_bounds__(256)
void gemm_mma_kernel(const float* __restrict__ A, const float* __restrict__ B,
                     float* __restrict__ C, int M, int N, int K)
{
    extern __shared__ float smem[];
    gemm_body(A, B, C, M, N, K, smem);
}

// ---------------------------------------------------------------------------
// 3D RoPE, fused q+k (blockIdx.y selects); writes tf32-rounded values.
// ---------------------------------------------------------------------------
__global__ void rope_kernel(float* __restrict__ xq, const float* __restrict__ cq,
                            float* __restrict__ xk, const float* __restrict__ ck)
{
    float* x            = blockIdx.y ? xk : xq;
    const float* coords = blockIdx.y ? ck : cq;

    const int total = NROWS * HEADS * 48;
    int idx = blockIdx.x * blockDim.x + threadIdx.x;
    if (idx >= total) return;

    int p  = idx % 48;
    int h  = (idx / 48) % HEADS;
    int bl = idx / (48 * HEADS);
    int axis = p >> 4;
    int j    = p & 15;

    float coord = coords[(size_t)bl * 3 + axis];
    float inv = expf(-(float)j * (1.0f / 16.0f) * logf(10000.0f));
    float ang = coord * inv;
    float s, c;
    sincosf(ang, &s, &c);

    float* base = x + (size_t)bl * DIMS + h * HD + axis * 32;
    float x1 = base[j];
    float x2 = base[j + 16];
    base[j]      = __uint_as_float(f2tf32(x1 * c - x2 * s));
    base[j + 16] = __uint_as_float(f2tf32(x1 * s + x2 * c));
}

// ---------------------------------------------------------------------------
// V transpose -> tf32 bits
// ---------------------------------------------------------------------------
__global__ __launch_bounds__(256)
void transpose_v_kernel(const float* __restrict__ v, uint32_t* __restrict__ vt)
{
    __shared__ float t[32][33];
    const int tx = threadIdx.x & 31;
    const int ty = threadIdx.x >> 5;
    const int c0 = blockIdx.x * 32;
    const int r0 = blockIdx.y * 32;

#pragma unroll
    for (int i = 0; i < 4; i++)
        t[ty + i * 8][tx] = v[(size_t)(r0 + ty + i * 8) * DIMS + c0 + tx];
    __syncthreads();

#pragma unroll
    for (int i = 0; i < 4; i++) {
        int c = c0 + ty + i * 8;
        int h = c / HD, d = c % HD;
        int b = r0 >> 11, tl = r0 & 2047;
        vt[((size_t)(b * HEADS + h) * HD + d) * SEQL + tl + tx] =
            f2tf32(t[tx][ty + i * 8]);
    }
}

// ---------------------------------------------------------------------------
// Flash attention on mma.sync tf32; BQ=128, BK=64, 256 threads (8 warps),
// double-buffered K/V cp.async pipeline.
// ---------------------------------------------------------------------------
#define BQ 128
#define BK 64
#define QP 100
#define VP 68
#define ATTN_SMEM_U32 (BQ*QP + 2*BK*QP + 2*HD*VP + BQ*VP)   // 47360
#define ATTN_SMEM_BYTES (ATTN_SMEM_U32 * 4)                  // 189440

__global__ __launch_bounds__(256)
void attn_mma_kernel(const float* __restrict__ q, const float* __restrict__ k,
                     const uint32_t* __restrict__ vt, float* __restrict__ O)
{
    extern __shared__ uint32_t smu[];
    uint32_t* sQ  = smu;                     // [128][100]
    uint32_t* sK  = sQ + BQ * QP;            // 2 x [64][100]
    uint32_t* sVT = sK + 2 * BK * QP;        // 2 x [96][68]
    uint32_t* sP  = sVT + 2 * HD * VP;       // [128][68]

    const int tid  = threadIdx.x;
    const int wid  = tid >> 5;
    const int lane = tid & 31;
    const int grp  = lane >> 2;
    const int thr  = lane & 3;
    const int wr   = wid * 16;               // warp row base (0..112)
    const int q0   = blockIdx.x * BQ;
    const int h    = blockIdx.y;
    const int b    = blockIdx.z;

    const uint32_t sQ_u  = smem_u32(sQ);
    const uint32_t sK_u  = smem_u32(sK);
    const uint32_t sVT_u = smem_u32(sVT);

    const float scale = rsqrtf((float)HD);

    const float*    Qb = q  + ((size_t)b * SEQL + q0) * DIMS + h * HD;
    const float*    Kb = k  + (size_t)b * SEQL * DIMS + h * HD;
    const uint32_t* Vb = vt + (size_t)(b * HEADS + h) * HD * SEQL;

    // Q tile: 128 rows x 24 16B-chunks = 3072
#pragma unroll
    for (int i = 0; i < 12; i++) {
        int idx = tid + i * 256;
        int r = idx / 24, c4 = idx % 24;
        cp_async16(sQ_u + (r * QP + c4 * 4) * 4, Qb + (size_t)r * DIMS + c4 * 4);
    }
    cp_async_commit();

#define PREF_KV(kb)                                                              \
    do {                                                                         \
        int _k0 = (kb) * BK;                                                     \
        uint32_t _dK = sK_u  + ((kb) & 1) * BK * QP * 4;                         \
        uint32_t _dV = sVT_u + ((kb) & 1) * HD * VP * 4;                         \
        _Pragma("unroll")                                                        \
        for (int _i = 0; _i < 6; _i++) {                                         \
            int _idx = tid + _i * 256;                                           \
            int _r = _idx / 24, _c4 = _idx % 24;                                 \
            cp_async16(_dK + (_r * QP + _c4 * 4) * 4,                            \
                       Kb + (size_t)(_k0 + _r) * DIMS + _c4 * 4);                \
        }                                                                        \
        _Pragma("unroll")                                                        \
        for (int _i = 0; _i < 6; _i++) {                                         \
            int _idx = tid + _i * 256;                                           \
            int _d = _idx / 16, _c4 = _idx % 16;                                 \
            cp_async16(_dV + (_d * VP + _c4 * 4) * 4,                            \
                       Vb + (size_t)_d * SEQL + _k0 + _c4 * 4);                  \
        }                                                                        \
        cp_async_commit();                                                       \
    } while (0)

    PREF_KV(0);

    float m0 = -1e30f, m1 = -1e30f, l0 = 0.f, l1 = 0.f;
    float o[12][4];
#pragma unroll
    for (int nt = 0; nt < 12; nt++)
#pragma unroll
        for (int i = 0; i < 4; i++) o[nt][i] = 0.f;

    const int NT = SEQL / BK;   // 32
    for (int kb = 0; kb < NT; kb++) {
        if (kb + 1 < NT) { PREF_KV(kb + 1); cp_async_wait<1>(); }
        else             { cp_async_wait<0>(); }
        __syncthreads();

        const uint32_t* cK = sK  + (kb & 1) * BK * QP;
        const uint32_t* cV = sVT + (kb & 1) * HD * VP;

        // ---- S = Q K^T (warp: 16 rows x 64 keys) ----
        float s[8][4];
#pragma unroll
        for (int nt = 0; nt < 8; nt++)
#pragma unroll
            for (int i = 0; i < 4; i++) s[nt][i] = 0.f;

#pragma unroll
        for (int ks = 0; ks < 12; ks++) {
            const int kk = ks * 8;
            uint32_t a0 = sQ[(wr + grp    ) * QP + kk + thr    ];
            uint32_t a1 = sQ[(wr + grp + 8) * QP + kk + thr    ];
            uint32_t a2 = sQ[(wr + grp    ) * QP + kk + thr + 4];
            uint32_t a3 = sQ[(wr + grp + 8) * QP + kk + thr + 4];
#pragma unroll
            for (int nt = 0; nt < 8; nt++) {
                uint32_t b0 = cK[(nt * 8 + grp) * QP + kk + thr    ];
                uint32_t b1 = cK[(nt * 8 + grp) * QP + kk + thr + 4];
                mma_tf32(s[nt][0], s[nt][1], s[nt][2], s[nt][3],
                         a0, a1, a2, a3, b0, b1);
            }
        }

        // ---- online softmax ----
        float mt0 = -1e30f, mt1 = -1e30f;
#pragma unroll
        for (int nt = 0; nt < 8; nt++) {
#pragma unroll
            for (int i = 0; i < 4; i++) s[nt][i] *= scale;
            mt0 = fmaxf(mt0, fmaxf(s[nt][0], s[nt][1]));
            mt1 = fmaxf(mt1, fmaxf(s[nt][2], s[nt][3]));
        }
        mt0 = fmaxf(mt0, __shfl_xor_sync(0xffffffffu, mt0, 1));
        mt0 = fmaxf(mt0, __shfl_xor_sync(0xffffffffu, mt0, 2));
        mt1 = fmaxf(mt1, __shfl_xor_sync(0xffffffffu, mt1, 1));
        mt1 = fmaxf(mt1, __shfl_xor_sync(0xffffffffu, mt1, 2));

        float mn0 = fmaxf(m0, mt0), mn1 = fmaxf(m1, mt1);
        float al0 = __expf(m0 - mn0), al1 = __expf(m1 - mn1);
        float ls0 = 0.f, ls1 = 0.f;

#pragma unroll
        for (int nt = 0; nt < 8; nt++) {
            float p0 = __expf(s[nt][0] - mn0);
            float p1 = __expf(s[nt][1] - mn0);
            float p2 = __expf(s[nt][2] - mn1);
            float p3 = __expf(s[nt][3] - mn1);
            ls0 += p0 + p1;
            ls1 += p2 + p3;
            uint2* w0 = (uint2*)&sP[(wr + grp    ) * VP + nt * 8 + thr * 2];
            uint2* w1 = (uint2*)&sP[(wr + grp + 8) * VP + nt * 8 + thr * 2];
            *w0 = make_uint2(f2tf32(p0), f2tf32(p1));
            *w1 = make_uint2(f2tf32(p2), f2tf32(p3));
        }
        ls0 += __shfl_xor_sync(0xffffffffu, ls0, 1);
        ls0 += __shfl_xor_sync(0xffffffffu, ls0, 2);
        ls1 += __shfl_xor_sync(0xffffffffu, ls1, 1);
        ls1 += __shfl_xor_sync(0xffffffffu, ls1, 2);

        l0 = l0 * al0 + ls0;  m0 = mn0;
        l1 = l1 * al1 + ls1;  m1 = mn1;
#pragma unroll
        for (int nt = 0; nt < 12; nt++) {
            o[nt][0] *= al0; o[nt][1] *= al0;
            o[nt][2] *= al1; o[nt][3] *= al1;
        }
        __syncwarp();

        // ---- O += P V ----
#pragma unroll
        for (int ks = 0; ks < 8; ks++) {
            const int kk = ks * 8;
            uint32_t a0 = sP[(wr + grp    ) * VP + kk + thr    ];
            uint32_t a1 = sP[(wr + grp + 8) * VP + kk + thr    ];
            uint32_t a2 = sP[(wr + grp    ) * VP + kk + thr + 4];
            uint32_t a3 = sP[(wr + grp + 8) * VP + kk + thr + 4];
#pragma unroll
            for (int nt = 0; nt < 12; nt++) {
                uint32_t b0 = cV[(nt * 8 + grp) * VP + kk + thr    ];
                uint32_t b1 = cV[(nt * 8 + grp) * VP + kk + thr + 4];
                mma_tf32(o[nt][0], o[nt][1], o[nt][2], o[nt][3],
                         a0, a1, a2, a3, b0, b1);
            }
        }
        __syncthreads();   // all warps done with this stage before reuse
    }
#undef PREF_KV

    // epilogue: normalize + tf32-round (feeds cvt-free Wo GEMM)
    float inv0 = 1.f / l0, inv1 = 1.f / l1;
    size_t row0 = ((size_t)b * SEQL + q0 + wr + grp    ) * DIMS + h * HD;
    size_t row1 = ((size_t)b * SEQL + q0 + wr + grp + 8) * DIMS + h * HD;
#pragma unroll
    for (int nt = 0; nt < 12; nt++) {
        int c = nt * 8 + thr * 2;
        *(float2*)(O + row0 + c) = make_float2(
            __uint_as_float(f2tf32(o[nt][0] * inv0)),
            __uint_as_float(f2tf32(o[nt][1] * inv0)));
        *(float2*)(O + row1 + c) = make_float2(
            __uint_as_float(f2tf32(o[nt][2] * inv1)),
            __uint_as_float(f2tf32(o[nt][3] * inv1)));
    }
}

// ---------------------------------------------------------------------------
// Launch
// ---------------------------------------------------------------------------
extern "C" void kernel_launch(void* const* d_in, const int* in_sizes, int n_in,
                              void* d_out, int out_size)
{
    const float* Q_in = (const float*)d_in[0];
    const float* K_in = (const float*)d_in[1];
    const float* V_in = (const float*)d_in[2];
    const float* cq   = (const float*)d_in[3];
    const float* ck   = (const float*)d_in[4];
    const float* Wq   = (const float*)d_in[5];
    const float* Wk   = (const float*)d_in[6];
    const float* Wv   = (const float*)d_in[7];
    const float* Wo   = (const float*)d_in[8];
    float* out = (float*)d_out;

    float *q, *k, *v, *att, *qin, *kin, *vin, *wq, *wk, *wv, *wo;
    uint32_t* vt;
    cudaGetSymbolAddress((void**)&q,   g_q);
    cudaGetSymbolAddress((void**)&k,   g_k);
    cudaGetSymbolAddress((void**)&v,   g_v);
    cudaGetSymbolAddress((void**)&att, g_att);
    cudaGetSymbolAddress((void**)&vt,  g_vt);
    cudaGetSymbolAddress((void**)&qin, g_qin);
    cudaGetSymbolAddress((void**)&kin, g_kin);
    cudaGetSymbolAddress((void**)&vin, g_vin);
    cudaGetSymbolAddress((void**)&wq,  g_wq);
    cudaGetSymbolAddress((void**)&wk,  g_wk);
    cudaGetSymbolAddress((void**)&wv,  g_wv);
    cudaGetSymbolAddress((void**)&wo,  g_wo);

    cudaFuncSetAttribute(gemm_qkv_kernel, cudaFuncAttributeMaxDynamicSharedMemorySize,
                         GEMM_SMEM_BYTES);
    cudaFuncSetAttribute(gemm_mma_kernel, cudaFuncAttributeMaxDynamicSharedMemorySize,
                         GEMM_SMEM_BYTES);
    cudaFuncSetAttribute(attn_mma_kernel, cudaFuncAttributeMaxDynamicSharedMemorySize,
                         ATTN_SMEM_BYTES);

    // tf32 pre-rounding
    round_inputs_kernel<<<dim3(NROWS * DIMS / 4 / 256, 3), 256>>>(
        Q_in, K_in, V_in, qin, kin, vin);
    round_weights_kernel<<<dim3(DIMS * DIMS / 4 / 256, 4), 256>>>(
        Wq, Wk, Wv, Wo, wq, wk, wv, wo);

    // fused Q/K/V projections (cvt-free)
    gemm_qkv_kernel<<<dim3(NROWS / TM, DIMS / TN, 3), 256, GEMM_SMEM_BYTES>>>(
        qin, kin, vin, wq, wk, wv, q, k, v);

    // RoPE (q+k fused) + V transpose
    {
        int total  = NROWS * HEADS * 48;
        int blocks = (total + 255) / 256;
        rope_kernel<<<dim3(blocks, 2), 256>>>(q, cq, k, ck);
    }
    transpose_v_kernel<<<dim3(DIMS / 32, NROWS / 32), 256>>>(v, vt);

    // tensor-core flash attention (writes tf32-rounded att)
    attn_mma_kernel<<<dim3(SEQL / BQ, HEADS, BATCH), 256, ATTN_SMEM_BYTES>>>(q, k, vt, att);

    // output projection (cvt-free)
    gemm_mma_kernel<<<dim3(NROWS / TM, DIMS / TN), 256, GEMM_SMEM_BYTES>>>(
        att, wo, out, NROWS, DIMS, DIMS);
}

// round 8
// speedup vs baseline: 1.0509x; 1.0509x over previous
#include <cuda_runtime.h>
#include <math.h>
#include <stdint.h>

#define DIMS   768
#define HEADS  8
#define HD     96
#define SEQL   2048
#define BATCH  2
#define NROWS  (BATCH*SEQL)   // 4096

// ---------------------------------------------------------------------------
// Scratch (static device globals: allocation-free, graph-capture safe)
// ---------------------------------------------------------------------------
__device__ float    g_q  [NROWS*DIMS];
__device__ float    g_k  [NROWS*DIMS];
__device__ float    g_v  [NROWS*DIMS];
__device__ float    g_att[NROWS*DIMS];
__device__ uint32_t g_vt [BATCH*HEADS*HD*SEQL];   // V^T, tf32 bits
// tf32-rounded copies of inputs/weights (cvt-free GEMM fragments)
__device__ float    g_qin[NROWS*DIMS];
__device__ float    g_kin[NROWS*DIMS];
__device__ float    g_vin[NROWS*DIMS];
__device__ float    g_wq [DIMS*DIMS];
__device__ float    g_wk [DIMS*DIMS];
__device__ float    g_wv [DIMS*DIMS];
__device__ float    g_wo [DIMS*DIMS];

// ---------------------------------------------------------------------------
// PTX helpers
// ---------------------------------------------------------------------------
__device__ __forceinline__ uint32_t smem_u32(const void* p) {
    uint32_t a;
    asm("{ .reg .u64 t; cvta.to.shared.u64 t, %1; cvt.u32.u64 %0, t; }" : "=r"(a) : "l"(p));
    return a;
}
__device__ __forceinline__ void cp_async16(uint32_t dst, const void* src) {
    asm volatile("cp.async.cg.shared.global [%0], [%1], 16;" :: "r"(dst), "l"(src));
}
__device__ __forceinline__ void cp_async_commit() { asm volatile("cp.async.commit_group;" ::: "memory"); }
template<int N>
__device__ __forceinline__ void cp_async_wait() { asm volatile("cp.async.wait_group %0;" :: "n"(N) : "memory"); }

__device__ __forceinline__ uint32_t f2tf32(float x) {
    uint32_t u;
    asm("cvt.rna.tf32.f32 %0, %1;" : "=r"(u) : "f"(x));
    return u;
}
__device__ __forceinline__ void mma_tf32(float& c0, float& c1, float& c2, float& c3,
                                         uint32_t a0, uint32_t a1, uint32_t a2, uint32_t a3,
                                         uint32_t b0, uint32_t b1) {
    asm volatile(
        "mma.sync.aligned.m16n8k8.row.col.f32.tf32.tf32.f32 "
        "{%0,%1,%2,%3}, {%4,%5,%6,%7}, {%8,%9}, {%0,%1,%2,%3};"
        : "+f"(c0), "+f"(c1), "+f"(c2), "+f"(c3)
        : "r"(a0), "r"(a1), "r"(a2), "r"(a3), "r"(b0), "r"(b1));
}

// ---------------------------------------------------------------------------
// tf32 pre-rounding passes (float4 vectorized)
// ---------------------------------------------------------------------------
__device__ __forceinline__ float4 round4(float4 x) {
    return make_float4(__uint_as_float(f2tf32(x.x)), __uint_as_float(f2tf32(x.y)),
                       __uint_as_float(f2tf32(x.z)), __uint_as_float(f2tf32(x.w)));
}
// inputs: 3 matrices [NROWS*DIMS], blockIdx.y selects
__global__ __launch_bounds__(256)
void round_inputs_kernel(const float* __restrict__ a, const float* __restrict__ b,
                         const float* __restrict__ c, float* __restrict__ oa,
                         float* __restrict__ ob, float* __restrict__ oc)
{
    const float* src; float* dst;
    if      (blockIdx.y == 0) { src = a; dst = oa; }
    else if (blockIdx.y == 1) { src = b; dst = ob; }
    else                      { src = c; dst = oc; }
    int i = blockIdx.x * 256 + threadIdx.x;            // float4 index
    ((float4*)dst)[i] = round4(((const float4*)src)[i]);
}
// weights: 4 matrices [DIMS*DIMS]
__global__ __launch_bounds__(256)
void round_weights_kernel(const float* __restrict__ a, const float* __restrict__ b,
                          const float* __restrict__ c, const float* __restrict__ d,
                          float* __restrict__ oa, float* __restrict__ ob,
                          float* __restrict__ oc, float* __restrict__ od)
{
    const float* src; float* dst;
    if      (blockIdx.y == 0) { src = a; dst = oa; }
    else if (blockIdx.y == 1) { src = b; dst = ob; }
    else if (blockIdx.y == 2) { src = c; dst = oc; }
    else                      { src = d; dst = od; }
    int i = blockIdx.x * 256 + threadIdx.x;
    ((float4*)dst)[i] = round4(((const float4*)src)[i]);
}

// ---------------------------------------------------------------------------
// NT GEMM via mma.sync tf32; operands PRE-ROUNDED to tf32 bits (no cvt in loop)
// ---------------------------------------------------------------------------
#define TM   128
#define TN   128
#define KCH  32
#define PITCH 36
#define STAGE_F (TM * PITCH)
#define GEMM_SMEM_BYTES (4 * STAGE_F * 4)   // 73728 B

__device__ __forceinline__
void gemm_body(const float* __restrict__ A, const float* __restrict__ B,
               float* __restrict__ C, int M, int N, int K, float* smem)
{
    float* sA = smem;
    float* sB = smem + 2 * STAGE_F;

    const int tid  = threadIdx.x;
    const int wid  = tid >> 5;
    const int lane = tid & 31;
    const int grp  = lane >> 2;
    const int thr  = lane & 3;
    const int wm   = (wid & 3) * 32;
    const int wn   = (wid >> 2) * 64;
    const int rowBase = blockIdx.x * TM;
    const int colBase = blockIdx.y * TN;

    const uint32_t sA_u = smem_u32(sA);
    const uint32_t sB_u = smem_u32(sB);

    float acc[2][8][4];
#pragma unroll
    for (int mt = 0; mt < 2; mt++)
#pragma unroll
        for (int nt = 0; nt < 8; nt++)
#pragma unroll
            for (int i = 0; i < 4; i++) acc[mt][nt][i] = 0.f;

    const int nChunks = K / KCH;

#define PREFETCH(ch)                                                            \
    do {                                                                        \
        int _k0 = (ch) * KCH;                                                   \
        uint32_t _dA = sA_u + ((ch) & 1) * STAGE_F * 4;                         \
        uint32_t _dB = sB_u + ((ch) & 1) * STAGE_F * 4;                         \
        _Pragma("unroll")                                                       \
        for (int _it = 0; _it < 4; _it++) {                                     \
            int _idx = tid + _it * 256;                                         \
            int _r = _idx >> 3, _seg = _idx & 7;                                \
            cp_async16(_dA + (_r * PITCH + _seg * 4) * 4,                       \
                       A + (size_t)(rowBase + _r) * K + _k0 + _seg * 4);        \
            cp_async16(_dB + (_r * PITCH + _seg * 4) * 4,                       \
                       B + (size_t)(colBase + _r) * K + _k0 + _seg * 4);        \
        }                                                                       \
        cp_async_commit();                                                      \
    } while (0)

    PREFETCH(0);

    for (int ch = 0; ch < nChunks; ch++) {
        if (ch + 1 < nChunks) { PREFETCH(ch + 1); cp_async_wait<1>(); }
        else                  { cp_async_wait<0>(); }
        __syncthreads();

        const float* cA = sA + (ch & 1) * STAGE_F;
        const float* cB = sB + (ch & 1) * STAGE_F;

#pragma unroll
        for (int ks = 0; ks < 4; ks++) {
            const int kk = ks * 8;
            uint32_t af[2][4];
#pragma unroll
            for (int mt = 0; mt < 2; mt++) {
                int rb = wm + mt * 16 + grp;
                af[mt][0] = __float_as_uint(cA[(rb    ) * PITCH + kk + thr    ]);
                af[mt][1] = __float_as_uint(cA[(rb + 8) * PITCH + kk + thr    ]);
                af[mt][2] = __float_as_uint(cA[(rb    ) * PITCH + kk + thr + 4]);
                af[mt][3] = __float_as_uint(cA[(rb + 8) * PITCH + kk + thr + 4]);
            }
            uint32_t bf[8][2];
#pragma unroll
            for (int nt = 0; nt < 8; nt++) {
                int cb = wn + nt * 8 + grp;
                bf[nt][0] = __float_as_uint(cB[cb * PITCH + kk + thr    ]);
                bf[nt][1] = __float_as_uint(cB[cb * PITCH + kk + thr + 4]);
            }
#pragma unroll
            for (int mt = 0; mt < 2; mt++)
#pragma unroll
                for (int nt = 0; nt < 8; nt++)
                    mma_tf32(acc[mt][nt][0], acc[mt][nt][1],
                             acc[mt][nt][2], acc[mt][nt][3],
                             af[mt][0], af[mt][1], af[mt][2], af[mt][3],
                             bf[nt][0], bf[nt][1]);
        }
        __syncthreads();
    }
#undef PREFETCH

#pragma unroll
    for (int mt = 0; mt < 2; mt++) {
        int r0 = rowBase + wm + mt * 16 + grp;
#pragma unroll
        for (int nt = 0; nt < 8; nt++) {
            int c0 = colBase + wn + nt * 8 + thr * 2;
            float2* p0 = (float2*)(C + (size_t)r0 * N + c0);
            float2* p1 = (float2*)(C + (size_t)(r0 + 8) * N + c0);
            *p0 = make_float2(acc[mt][nt][0], acc[mt][nt][1]);
            *p1 = make_float2(acc[mt][nt][2], acc[mt][nt][3]);
        }
    }
}

__global__ __launch_bounds__(256)
void gemm_qkv_kernel(const float* __restrict__ Qin, const float* __restrict__ Kin,
                     const float* __restrict__ Vin, const float* __restrict__ Wq,
                     const float* __restrict__ Wk, const float* __restrict__ Wv,
                     float* __restrict__ q, float* __restrict__ k, float* __restrict__ v)
{
    extern __shared__ float smem[];
    const float *A, *B;
    float* C;
    if      (blockIdx.z == 0) { A = Qin; B = Wq; C = q; }
    else if (blockIdx.z == 1) { A = Kin; B = Wk; C = k; }
    else                      { A = Vin; B = Wv; C = v; }
    gemm_body(A, B, C, NROWS, DIMS, DIMS, smem);
}

__global__ __launch_bounds__(256)
void gemm_mma_kernel(const float* __restrict__ A, const float* __restrict__ B,
                     float* __restrict__ C, int M, int N, int K)
{
    extern __shared__ float smem[];
    gemm_body(A, B, C, M, N, K, smem);
}

// ---------------------------------------------------------------------------
// 3D RoPE, fused q+k (blockIdx.y selects); writes tf32-rounded values.
// ---------------------------------------------------------------------------
__global__ void rope_kernel(float* __restrict__ xq, const float* __restrict__ cq,
                            float* __restrict__ xk, const float* __restrict__ ck)
{
    float* x            = blockIdx.y ? xk : xq;
    const float* coords = blockIdx.y ? ck : cq;

    const int total = NROWS * HEADS * 48;
    int idx = blockIdx.x * blockDim.x + threadIdx.x;
    if (idx >= total) return;

    int p  = idx % 48;
    int h  = (idx / 48) % HEADS;
    int bl = idx / (48 * HEADS);
    int axis = p >> 4;
    int j    = p & 15;

    float coord = coords[(size_t)bl * 3 + axis];
    float inv = expf(-(float)j * (1.0f / 16.0f) * logf(10000.0f));
    float ang = coord * inv;
    float s, c;
    sincosf(ang, &s, &c);

    float* base = x + (size_t)bl * DIMS + h * HD + axis * 32;
    float x1 = base[j];
    float x2 = base[j + 16];
    base[j]      = __uint_as_float(f2tf32(x1 * c - x2 * s));
    base[j + 16] = __uint_as_float(f2tf32(x1 * s + x2 * c));
}

// ---------------------------------------------------------------------------
// V transpose -> tf32 bits
// ---------------------------------------------------------------------------
__global__ __launch_bounds__(256)
void transpose_v_kernel(const float* __restrict__ v, uint32_t* __restrict__ vt)
{
    __shared__ float t[32][33];
    const int tx = threadIdx.x & 31;
    const int ty = threadIdx.x >> 5;
    const int c0 = blockIdx.x * 32;
    const int r0 = blockIdx.y * 32;

#pragma unroll
    for (int i = 0; i < 4; i++)
        t[ty + i * 8][tx] = v[(size_t)(r0 + ty + i * 8) * DIMS + c0 + tx];
    __syncthreads();

#pragma unroll
    for (int i = 0; i < 4; i++) {
        int c = c0 + ty + i * 8;
        int h = c / HD, d = c % HD;
        int b = r0 >> 11, tl = r0 & 2047;
        vt[((size_t)(b * HEADS + h) * HD + d) * SEQL + tl + tx] =
            f2tf32(t[tx][ty + i * 8]);
    }
}

// ---------------------------------------------------------------------------
// Flash attention on mma.sync tf32 — R4 shape: BQ=64, BK=64, 128 threads
// (4 warps, warp-M=16), single-buffered K/V, 94.7KB smem -> 2 CTAs/SM.
// Epilogue writes tf32-rounded att (feeds cvt-free Wo GEMM).
// ---------------------------------------------------------------------------
#define BQ 64
#define BK 64
#define QP 100
#define VP 68
#define ATTN_SMEM_U32 (BQ*QP + BK*QP + HD*VP + BQ*VP)       // 23680
#define ATTN_SMEM_BYTES (ATTN_SMEM_U32 * 4)                 // 94720

__global__ __launch_bounds__(128)
void attn_mma_kernel(const float* __restrict__ q, const float* __restrict__ k,
                     const uint32_t* __restrict__ vt, float* __restrict__ O)
{
    extern __shared__ uint32_t smu[];
    uint32_t* sQ  = smu;                     // [64][100]
    uint32_t* sK  = sQ + BQ * QP;            // [64][100]
    uint32_t* sVT = sK + BK * QP;            // [96][68]
    uint32_t* sP  = sVT + HD * VP;           // [64][68]

    const int tid  = threadIdx.x;
    const int wid  = tid >> 5;
    const int lane = tid & 31;
    const int grp  = lane >> 2;
    const int thr  = lane & 3;
    const int wr   = wid * 16;
    const int q0   = blockIdx.x * BQ;
    const int h    = blockIdx.y;
    const int b    = blockIdx.z;

    const uint32_t sQ_u  = smem_u32(sQ);
    const uint32_t sK_u  = smem_u32(sK);
    const uint32_t sVT_u = smem_u32(sVT);

    const float scale = rsqrtf((float)HD);

    const float*    Qb = q  + ((size_t)b * SEQL + q0) * DIMS + h * HD;
    const float*    Kb = k  + (size_t)b * SEQL * DIMS + h * HD;
    const uint32_t* Vb = vt + (size_t)(b * HEADS + h) * HD * SEQL;

    // Q tile: 64 rows x 24 16B-chunks = 1536
#pragma unroll
    for (int i = 0; i < 12; i++) {
        int idx = tid + i * 128;
        int r = idx / 24, c4 = idx % 24;
        cp_async16(sQ_u + (r * QP + c4 * 4) * 4, Qb + (size_t)r * DIMS + c4 * 4);
    }
    cp_async_commit();

    float m0 = -1e30f, m1 = -1e30f, l0 = 0.f, l1 = 0.f;
    float o[12][4];
#pragma unroll
    for (int nt = 0; nt < 12; nt++)
#pragma unroll
        for (int i = 0; i < 4; i++) o[nt][i] = 0.f;

    for (int kb = 0; kb < SEQL / BK; kb++) {
        const int k0 = kb * BK;
        __syncthreads();   // previous iteration done with sK/sVT/sP
#pragma unroll
        for (int i = 0; i < 12; i++) {
            int idx = tid + i * 128;
            int r = idx / 24, c4 = idx % 24;
            cp_async16(sK_u + (r * QP + c4 * 4) * 4,
                       Kb + (size_t)(k0 + r) * DIMS + c4 * 4);
        }
#pragma unroll
        for (int i = 0; i < 12; i++) {
            int idx = tid + i * 128;
            int d = idx / 16, c4 = idx % 16;
            cp_async16(sVT_u + (d * VP + c4 * 4) * 4,
                       Vb + (size_t)d * SEQL + k0 + c4 * 4);
        }
        cp_async_commit();
        cp_async_wait<0>();
        __syncthreads();

        // ---- S = Q K^T (warp: 16 rows x 64 keys) ----
        float s[8][4];
#pragma unroll
        for (int nt = 0; nt < 8; nt++)
#pragma unroll
            for (int i = 0; i < 4; i++) s[nt][i] = 0.f;

#pragma unroll
        for (int ks = 0; ks < 12; ks++) {
            const int kk = ks * 8;
            uint32_t a0 = sQ[(wr + grp    ) * QP + kk + thr    ];
            uint32_t a1 = sQ[(wr + grp + 8) * QP + kk + thr    ];
            uint32_t a2 = sQ[(wr + grp    ) * QP + kk + thr + 4];
            uint32_t a3 = sQ[(wr + grp + 8) * QP + kk + thr + 4];
#pragma unroll
            for (int nt = 0; nt < 8; nt++) {
                uint32_t b0 = sK[(nt * 8 + grp) * QP + kk + thr    ];
                uint32_t b1 = sK[(nt * 8 + grp) * QP + kk + thr + 4];
                mma_tf32(s[nt][0], s[nt][1], s[nt][2], s[nt][3],
                         a0, a1, a2, a3, b0, b1);
            }
        }

        // ---- online softmax (rows grp and grp+8) ----
        float mt0 = -1e30f, mt1 = -1e30f;
#pragma unroll
        for (int nt = 0; nt < 8; nt++) {
#pragma unroll
            for (int i = 0; i < 4; i++) s[nt][i] *= scale;
            mt0 = fmaxf(mt0, fmaxf(s[nt][0], s[nt][1]));
            mt1 = fmaxf(mt1, fmaxf(s[nt][2], s[nt][3]));
        }
        mt0 = fmaxf(mt0, __shfl_xor_sync(0xffffffffu, mt0, 1));
        mt0 = fmaxf(mt0, __shfl_xor_sync(0xffffffffu, mt0, 2));
        mt1 = fmaxf(mt1, __shfl_xor_sync(0xffffffffu, mt1, 1));
        mt1 = fmaxf(mt1, __shfl_xor_sync(0xffffffffu, mt1, 2));

        float mn0 = fmaxf(m0, mt0), mn1 = fmaxf(m1, mt1);
        float al0 = __expf(m0 - mn0), al1 = __expf(m1 - mn1);
        float ls0 = 0.f, ls1 = 0.f;

#pragma unroll
        for (int nt = 0; nt < 8; nt++) {
            float p0 = __expf(s[nt][0] - mn0);
            float p1 = __expf(s[nt][1] - mn0);
            float p2 = __expf(s[nt][2] - mn1);
            float p3 = __expf(s[nt][3] - mn1);
            ls0 += p0 + p1;
            ls1 += p2 + p3;
            uint2* w0 = (uint2*)&sP[(wr + grp    ) * VP + nt * 8 + thr * 2];
            uint2* w1 = (uint2*)&sP[(wr + grp + 8) * VP + nt * 8 + thr * 2];
            *w0 = make_uint2(f2tf32(p0), f2tf32(p1));
            *w1 = make_uint2(f2tf32(p2), f2tf32(p3));
        }
        ls0 += __shfl_xor_sync(0xffffffffu, ls0, 1);
        ls0 += __shfl_xor_sync(0xffffffffu, ls0, 2);
        ls1 += __shfl_xor_sync(0xffffffffu, ls1, 1);
        ls1 += __shfl_xor_sync(0xffffffffu, ls1, 2);

        l0 = l0 * al0 + ls0;  m0 = mn0;
        l1 = l1 * al1 + ls1;  m1 = mn1;
#pragma unroll
        for (int nt = 0; nt < 12; nt++) {
            o[nt][0] *= al0; o[nt][1] *= al0;
            o[nt][2] *= al1; o[nt][3] *= al1;
        }
        __syncwarp();

        // ---- O += P V ----
#pragma unroll
        for (int ks = 0; ks < 8; ks++) {
            const int kk = ks * 8;
            uint32_t a0 = sP[(wr + grp    ) * VP + kk + thr    ];
            uint32_t a1 = sP[(wr + grp + 8) * VP + kk + thr    ];
            uint32_t a2 = sP[(wr + grp    ) * VP + kk + thr + 4];
            uint32_t a3 = sP[(wr + grp + 8) * VP + kk + thr + 4];
#pragma unroll
            for (int nt = 0; nt < 12; nt++) {
                uint32_t b0 = sVT[(nt * 8 + grp) * VP + kk + thr    ];
                uint32_t b1 = sVT[(nt * 8 + grp) * VP + kk + thr + 4];
                mma_tf32(o[nt][0], o[nt][1], o[nt][2], o[nt][3],
                         a0, a1, a2, a3, b0, b1);
            }
        }
    }

    // epilogue: normalize + tf32-round (feeds cvt-free Wo GEMM)
    float inv0 = 1.f / l0, inv1 = 1.f / l1;
    size_t row0 = ((size_t)b * SEQL + q0 + wr + grp    ) * DIMS + h * HD;
    size_t row1 = ((size_t)b * SEQL + q0 + wr + grp + 8) * DIMS + h * HD;
#pragma unroll
    for (int nt = 0; nt < 12; nt++) {
        int c = nt * 8 + thr * 2;
        *(float2*)(O + row0 + c) = make_float2(
            __uint_as_float(f2tf32(o[nt][0] * inv0)),
            __uint_as_float(f2tf32(o[nt][1] * inv0)));
        *(float2*)(O + row1 + c) = make_float2(
            __uint_as_float(f2tf32(o[nt][2] * inv1)),
            __uint_as_float(f2tf32(o[nt][3] * inv1)));
    }
}

// ---------------------------------------------------------------------------
// Launch
// ---------------------------------------------------------------------------
extern "C" void kernel_launch(void* const* d_in, const int* in_sizes, int n_in,
                              void* d_out, int out_size)
{
    const float* Q_in = (const float*)d_in[0];
    const float* K_in = (const float*)d_in[1];
    const float* V_in = (const float*)d_in[2];
    const float* cq   = (const float*)d_in[3];
    const float* ck   = (const float*)d_in[4];
    const float* Wq   = (const float*)d_in[5];
    const float* Wk   = (const float*)d_in[6];
    const float* Wv   = (const float*)d_in[7];
    const float* Wo   = (const float*)d_in[8];
    float* out = (float*)d_out;

    float *q, *k, *v, *att, *qin, *kin, *vin, *wq, *wk, *wv, *wo;
    uint32_t* vt;
    cudaGetSymbolAddress((void**)&q,   g_q);
    cudaGetSymbolAddress((void**)&k,   g_k);
    cudaGetSymbolAddress((void**)&v,   g_v);
    cudaGetSymbolAddress((void**)&att, g_att);
    cudaGetSymbolAddress((void**)&vt,  g_vt);
    cudaGetSymbolAddress((void**)&qin, g_qin);
    cudaGetSymbolAddress((void**)&kin, g_kin);
    cudaGetSymbolAddress((void**)&vin, g_vin);
    cudaGetSymbolAddress((void**)&wq,  g_wq);
    cudaGetSymbolAddress((void**)&wk,  g_wk);
    cudaGetSymbolAddress((void**)&wv,  g_wv);
    cudaGetSymbolAddress((void**)&wo,  g_wo);

    cudaFuncSetAttribute(gemm_qkv_kernel, cudaFuncAttributeMaxDynamicSharedMemorySize,
                         GEMM_SMEM_BYTES);
    cudaFuncSetAttribute(gemm_mma_kernel, cudaFuncAttributeMaxDynamicSharedMemorySize,
                         GEMM_SMEM_BYTES);
    cudaFuncSetAttribute(attn_mma_kernel, cudaFuncAttributeMaxDynamicSharedMemorySize,
                         ATTN_SMEM_BYTES);

    // tf32 pre-rounding
    round_inputs_kernel<<<dim3(NROWS * DIMS / 4 / 256, 3), 256>>>(
        Q_in, K_in, V_in, qin, kin, vin);
    round_weights_kernel<<<dim3(DIMS * DIMS / 4 / 256, 4), 256>>>(
        Wq, Wk, Wv, Wo, wq, wk, wv, wo);

    // fused Q/K/V projections (cvt-free)
    gemm_qkv_kernel<<<dim3(NROWS / TM, DIMS / TN, 3), 256, GEMM_SMEM_BYTES>>>(
        qin, kin, vin, wq, wk, wv, q, k, v);

    // RoPE (q+k fused) + V transpose
    {
        int total  = NROWS * HEADS * 48;
        int blocks = (total + 255) / 256;
        rope_kernel<<<dim3(blocks, 2), 256>>>(q, cq, k, ck);
    }
    transpose_v_kernel<<<dim3(DIMS / 32, NROWS / 32), 256>>>(v, vt);

    // tensor-core flash attention (2 CTAs/SM)
    attn_mma_kernel<<<dim3(SEQL / BQ, HEADS, BATCH), 128, ATTN_SMEM_BYTES>>>(q, k, vt, att);

    // output projection (cvt-free)
    gemm_mma_kernel<<<dim3(NROWS / TM, DIMS / TN), 256, GEMM_SMEM_BYTES>>>(
        att, wo, out, NROWS, DIMS, DIMS);
}

// round 9
// speedup vs baseline: 1.0913x; 1.0384x over previous
#include <cuda_runtime.h>
#include <math.h>
#include <stdint.h>

#define DIMS   768
#define HEADS  8
#define HD     96
#define SEQL   2048
#define BATCH  2
#define NROWS  (BATCH*SEQL)   // 4096

// ---------------------------------------------------------------------------
// Scratch (static device globals: allocation-free, graph-capture safe)
// ---------------------------------------------------------------------------
__device__ float    g_q  [NROWS*DIMS];
__device__ float    g_k  [NROWS*DIMS];
__device__ float    g_v  [NROWS*DIMS];
__device__ float    g_att[NROWS*DIMS];
__device__ uint32_t g_vt [BATCH*HEADS*HD*SEQL];   // V^T, tf32 bits
// tf32-rounded weights (cvt-free B fragments)
__device__ float    g_wq [DIMS*DIMS];
__device__ float    g_wk [DIMS*DIMS];
__device__ float    g_wv [DIMS*DIMS];
__device__ float    g_wo [DIMS*DIMS];

// ---------------------------------------------------------------------------
// PTX helpers
// ---------------------------------------------------------------------------
__device__ __forceinline__ uint32_t smem_u32(const void* p) {
    uint32_t a;
    asm("{ .reg .u64 t; cvta.to.shared.u64 t, %1; cvt.u32.u64 %0, t; }" : "=r"(a) : "l"(p));
    return a;
}
__device__ __forceinline__ void cp_async16(uint32_t dst, const void* src) {
    asm volatile("cp.async.cg.shared.global [%0], [%1], 16;" :: "r"(dst), "l"(src));
}
__device__ __forceinline__ void cp_async_commit() { asm volatile("cp.async.commit_group;" ::: "memory"); }
template<int N>
__device__ __forceinline__ void cp_async_wait() { asm volatile("cp.async.wait_group %0;" :: "n"(N) : "memory"); }

__device__ __forceinline__ uint32_t f2tf32(float x) {
    uint32_t u;
    asm("cvt.rna.tf32.f32 %0, %1;" : "=r"(u) : "f"(x));
    return u;
}
__device__ __forceinline__ void mma_tf32(float& c0, float& c1, float& c2, float& c3,
                                         uint32_t a0, uint32_t a1, uint32_t a2, uint32_t a3,
                                         uint32_t b0, uint32_t b1) {
    asm volatile(
        "mma.sync.aligned.m16n8k8.row.col.f32.tf32.tf32.f32 "
        "{%0,%1,%2,%3}, {%4,%5,%6,%7}, {%8,%9}, {%0,%1,%2,%3};"
        : "+f"(c0), "+f"(c1), "+f"(c2), "+f"(c3)
        : "r"(a0), "r"(a1), "r"(a2), "r"(a3), "r"(b0), "r"(b1));
}

// ---------------------------------------------------------------------------
// tf32 pre-rounding of the 4 weight matrices (float4 vectorized, tiny)
// ---------------------------------------------------------------------------
__device__ __forceinline__ float4 round4(float4 x) {
    return make_float4(__uint_as_float(f2tf32(x.x)), __uint_as_float(f2tf32(x.y)),
                       __uint_as_float(f2tf32(x.z)), __uint_as_float(f2tf32(x.w)));
}
__global__ __launch_bounds__(256)
void round_weights_kernel(const float* __restrict__ a, const float* __restrict__ b,
                          const float* __restrict__ c, const float* __restrict__ d,
                          float* __restrict__ oa, float* __restrict__ ob,
                          float* __restrict__ oc, float* __restrict__ od)
{
    const float* src; float* dst;
    if      (blockIdx.y == 0) { src = a; dst = oa; }
    else if (blockIdx.y == 1) { src = b; dst = ob; }
    else if (blockIdx.y == 2) { src = c; dst = oc; }
    else                      { src = d; dst = od; }
    int i = blockIdx.x * 256 + threadIdx.x;
    ((float4*)dst)[i] = round4(((const float4*)src)[i]);
}

// ---------------------------------------------------------------------------
// NT GEMM via mma.sync tf32. B (weights) pre-rounded; A converted in-loop
// iff CVT_A (raw fp32 inputs) else bit-passthrough (already tf32-rounded).
// CTA 128x128, 256 threads, warp tile 32x64, 3-stage cp.async pipeline.
// ---------------------------------------------------------------------------
#define TM   128
#define TN   128
#define KCH  32
#define PITCH 36
#define NSTAGE 3
#define STAGE_F (TM * PITCH)
#define GEMM_SMEM_BYTES (2 * NSTAGE * STAGE_F * 4)   // 110592 B

template<bool CVT_A>
__device__ __forceinline__
void gemm_body(const float* __restrict__ A, const float* __restrict__ B,
               float* __restrict__ C, int M, int N, int K, float* smem)
{
    float* sA = smem;
    float* sB = smem + NSTAGE * STAGE_F;

    const int tid  = threadIdx.x;
    const int wid  = tid >> 5;
    const int lane = tid & 31;
    const int grp  = lane >> 2;
    const int thr  = lane & 3;
    const int wm   = (wid & 3) * 32;
    const int wn   = (wid >> 2) * 64;
    const int rowBase = blockIdx.x * TM;
    const int colBase = blockIdx.y * TN;

    const uint32_t sA_u = smem_u32(sA);
    const uint32_t sB_u = smem_u32(sB);

    float acc[2][8][4];
#pragma unroll
    for (int mt = 0; mt < 2; mt++)
#pragma unroll
        for (int nt = 0; nt < 8; nt++)
#pragma unroll
            for (int i = 0; i < 4; i++) acc[mt][nt][i] = 0.f;

    const int nChunks = K / KCH;   // 24

#define PREFETCH(ch)                                                            \
    do {                                                                        \
        int _k0 = (ch) * KCH;                                                   \
        uint32_t _dA = sA_u + ((ch) % NSTAGE) * STAGE_F * 4;                    \
        uint32_t _dB = sB_u + ((ch) % NSTAGE) * STAGE_F * 4;                    \
        _Pragma("unroll")                                                       \
        for (int _it = 0; _it < 4; _it++) {                                     \
            int _idx = tid + _it * 256;                                         \
            int _r = _idx >> 3, _seg = _idx & 7;                                \
            cp_async16(_dA + (_r * PITCH + _seg * 4) * 4,                       \
                       A + (size_t)(rowBase + _r) * K + _k0 + _seg * 4);        \
            cp_async16(_dB + (_r * PITCH + _seg * 4) * 4,                       \
                       B + (size_t)(colBase + _r) * K + _k0 + _seg * 4);        \
        }                                                                       \
        cp_async_commit();                                                      \
    } while (0)

    PREFETCH(0);
    PREFETCH(1);

    for (int ch = 0; ch < nChunks; ch++) {
        if      (ch + 2 < nChunks) { PREFETCH(ch + 2); cp_async_wait<2>(); }
        else if (ch + 1 < nChunks) { cp_async_wait<1>(); }
        else                       { cp_async_wait<0>(); }
        __syncthreads();

        const float* cA = sA + (ch % NSTAGE) * STAGE_F;
        const float* cB = sB + (ch % NSTAGE) * STAGE_F;

#pragma unroll
        for (int ks = 0; ks < 4; ks++) {
            const int kk = ks * 8;
            uint32_t af[2][4];
#pragma unroll
            for (int mt = 0; mt < 2; mt++) {
                int rb = wm + mt * 16 + grp;
                float a0 = cA[(rb    ) * PITCH + kk + thr    ];
                float a1 = cA[(rb + 8) * PITCH + kk + thr    ];
                float a2 = cA[(rb    ) * PITCH + kk + thr + 4];
                float a3 = cA[(rb + 8) * PITCH + kk + thr + 4];
                if (CVT_A) {
                    af[mt][0] = f2tf32(a0); af[mt][1] = f2tf32(a1);
                    af[mt][2] = f2tf32(a2); af[mt][3] = f2tf32(a3);
                } else {
                    af[mt][0] = __float_as_uint(a0); af[mt][1] = __float_as_uint(a1);
                    af[mt][2] = __float_as_uint(a2); af[mt][3] = __float_as_uint(a3);
                }
            }
            uint32_t bf[8][2];
#pragma unroll
            for (int nt = 0; nt < 8; nt++) {
                int cb = wn + nt * 8 + grp;
                bf[nt][0] = __float_as_uint(cB[cb * PITCH + kk + thr    ]);
                bf[nt][1] = __float_as_uint(cB[cb * PITCH + kk + thr + 4]);
            }
#pragma unroll
            for (int mt = 0; mt < 2; mt++)
#pragma unroll
                for (int nt = 0; nt < 8; nt++)
                    mma_tf32(acc[mt][nt][0], acc[mt][nt][1],
                             acc[mt][nt][2], acc[mt][nt][3],
                             af[mt][0], af[mt][1], af[mt][2], af[mt][3],
                             bf[nt][0], bf[nt][1]);
        }
        __syncthreads();
    }
#undef PREFETCH

#pragma unroll
    for (int mt = 0; mt < 2; mt++) {
        int r0 = rowBase + wm + mt * 16 + grp;
#pragma unroll
        for (int nt = 0; nt < 8; nt++) {
            int c0 = colBase + wn + nt * 8 + thr * 2;
            float2* p0 = (float2*)(C + (size_t)r0 * N + c0);
            float2* p1 = (float2*)(C + (size_t)(r0 + 8) * N + c0);
            *p0 = make_float2(acc[mt][nt][0], acc[mt][nt][1]);
            *p1 = make_float2(acc[mt][nt][2], acc[mt][nt][3]);
        }
    }
}

// QKV projections: raw fp32 A inputs -> in-loop A cvt
__global__ __launch_bounds__(256)
void gemm_qkv_kernel(const float* __restrict__ Qin, const float* __restrict__ Kin,
                     const float* __restrict__ Vin, const float* __restrict__ Wq,
                     const float* __restrict__ Wk, const float* __restrict__ Wv,
                     float* __restrict__ q, float* __restrict__ k, float* __restrict__ v)
{
    extern __shared__ float smem[];
    const float *A, *B;
    float* C;
    if      (blockIdx.z == 0) { A = Qin; B = Wq; C = q; }
    else if (blockIdx.z == 1) { A = Kin; B = Wk; C = k; }
    else                      { A = Vin; B = Wv; C = v; }
    gemm_body<true>(A, B, C, NROWS, DIMS, DIMS, smem);
}

// Wo projection: A = att already tf32-rounded -> cvt-free
__global__ __launch_bounds__(256)
void gemm_wo_kernel(const float* __restrict__ A, const float* __restrict__ B,
                    float* __restrict__ C)
{
    extern __shared__ float smem[];
    gemm_body<false>(A, B, C, NROWS, DIMS, DIMS, smem);
}

// ---------------------------------------------------------------------------
// Fused pointwise stage: z=0 rope(q), z=1 rope(k), z=2 transpose(v)->vt.
// Writes tf32-rounded values everywhere (feeds MMA consumers directly).
// ---------------------------------------------------------------------------
#define ROPE_BLOCKS ((NROWS * HEADS * 48) / 256)     // 6144
#define TRANS_BLOCKS ((DIMS / 32) * (NROWS / 32))    // 3072

__global__ __launch_bounds__(256)
void pointwise_kernel(float* __restrict__ xq, const float* __restrict__ cq,
                      float* __restrict__ xk, const float* __restrict__ ck,
                      const float* __restrict__ v, uint32_t* __restrict__ vt)
{
    __shared__ float t[32][33];
    const int z = blockIdx.y;

    if (z < 2) {
        float* x            = z ? xk : xq;
        const float* coords = z ? ck : cq;

        int idx = blockIdx.x * 256 + threadIdx.x;
        int p  = idx % 48;
        int h  = (idx / 48) % HEADS;
        int bl = idx / (48 * HEADS);
        int axis = p >> 4;
        int j    = p & 15;

        float coord = coords[(size_t)bl * 3 + axis];
        float inv = exp2f(-(float)j * (0.0625f * 13.28771238f));  // log2(1e4)/16
        float ang = coord * inv;
        float s, c;
        sincosf(ang, &s, &c);

        float* base = x + (size_t)bl * DIMS + h * HD + axis * 32;
        float x1 = base[j];
        float x2 = base[j + 16];
        base[j]      = __uint_as_float(f2tf32(x1 * c - x2 * s));
        base[j + 16] = __uint_as_float(f2tf32(x1 * s + x2 * c));
    } else {
        if (blockIdx.x >= TRANS_BLOCKS) return;
        const int tx = threadIdx.x & 31;
        const int ty = threadIdx.x >> 5;
        const int c0 = (blockIdx.x % (DIMS / 32)) * 32;
        const int r0 = (blockIdx.x / (DIMS / 32)) * 32;

#pragma unroll
        for (int i = 0; i < 4; i++)
            t[ty + i * 8][tx] = v[(size_t)(r0 + ty + i * 8) * DIMS + c0 + tx];
        __syncthreads();

#pragma unroll
        for (int i = 0; i < 4; i++) {
            int c = c0 + ty + i * 8;
            int h = c / HD, d = c % HD;
            int b = r0 >> 11, tl = r0 & 2047;
            vt[((size_t)(b * HEADS + h) * HD + d) * SEQL + tl + tx] =
                f2tf32(t[tx][ty + i * 8]);
        }
    }
}

// ---------------------------------------------------------------------------
// Flash attention on mma.sync tf32 — R8 shape (best known): BQ=64, BK=64,
// 128 threads, single-buffered, 94.7KB smem -> 2 CTAs/SM.
// ---------------------------------------------------------------------------
#define BQ 64
#define BK 64
#define QP 100
#define VP 68
#define ATTN_SMEM_U32 (BQ*QP + BK*QP + HD*VP + BQ*VP)       // 23680
#define ATTN_SMEM_BYTES (ATTN_SMEM_U32 * 4)                 // 94720

__global__ __launch_bounds__(128)
void attn_mma_kernel(const float* __restrict__ q, const float* __restrict__ k,
                     const uint32_t* __restrict__ vt, float* __restrict__ O)
{
    extern __shared__ uint32_t smu[];
    uint32_t* sQ  = smu;
    uint32_t* sK  = sQ + BQ * QP;
    uint32_t* sVT = sK + BK * QP;
    uint32_t* sP  = sVT + HD * VP;

    const int tid  = threadIdx.x;
    const int wid  = tid >> 5;
    const int lane = tid & 31;
    const int grp  = lane >> 2;
    const int thr  = lane & 3;
    const int wr   = wid * 16;
    const int q0   = blockIdx.x * BQ;
    const int h    = blockIdx.y;
    const int b    = blockIdx.z;

    const uint32_t sQ_u  = smem_u32(sQ);
    const uint32_t sK_u  = smem_u32(sK);
    const uint32_t sVT_u = smem_u32(sVT);

    const float scale = rsqrtf((float)HD);

    const float*    Qb = q  + ((size_t)b * SEQL + q0) * DIMS + h * HD;
    const float*    Kb = k  + (size_t)b * SEQL * DIMS + h * HD;
    const uint32_t* Vb = vt + (size_t)(b * HEADS + h) * HD * SEQL;

#pragma unroll
    for (int i = 0; i < 12; i++) {
        int idx = tid + i * 128;
        int r = idx / 24, c4 = idx % 24;
        cp_async16(sQ_u + (r * QP + c4 * 4) * 4, Qb + (size_t)r * DIMS + c4 * 4);
    }
    cp_async_commit();

    float m0 = -1e30f, m1 = -1e30f, l0 = 0.f, l1 = 0.f;
    float o[12][4];
#pragma unroll
    for (int nt = 0; nt < 12; nt++)
#pragma unroll
        for (int i = 0; i < 4; i++) o[nt][i] = 0.f;

    for (int kb = 0; kb < SEQL / BK; kb++) {
        const int k0 = kb * BK;
        __syncthreads();
#pragma unroll
        for (int i = 0; i < 12; i++) {
            int idx = tid + i * 128;
            int r = idx / 24, c4 = idx % 24;
            cp_async16(sK_u + (r * QP + c4 * 4) * 4,
                       Kb + (size_t)(k0 + r) * DIMS + c4 * 4);
        }
#pragma unroll
        for (int i = 0; i < 12; i++) {
            int idx = tid + i * 128;
            int d = idx / 16, c4 = idx % 16;
            cp_async16(sVT_u + (d * VP + c4 * 4) * 4,
                       Vb + (size_t)d * SEQL + k0 + c4 * 4);
        }
        cp_async_commit();
        cp_async_wait<0>();
        __syncthreads();

        // ---- S = Q K^T ----
        float s[8][4];
#pragma unroll
        for (int nt = 0; nt < 8; nt++)
#pragma unroll
            for (int i = 0; i < 4; i++) s[nt][i] = 0.f;

#pragma unroll
        for (int ks = 0; ks < 12; ks++) {
            const int kk = ks * 8;
            uint32_t a0 = sQ[(wr + grp    ) * QP + kk + thr    ];
            uint32_t a1 = sQ[(wr + grp + 8) * QP + kk + thr    ];
            uint32_t a2 = sQ[(wr + grp    ) * QP + kk + thr + 4];
            uint32_t a3 = sQ[(wr + grp + 8) * QP + kk + thr + 4];
#pragma unroll
            for (int nt = 0; nt < 8; nt++) {
                uint32_t b0 = sK[(nt * 8 + grp) * QP + kk + thr    ];
                uint32_t b1 = sK[(nt * 8 + grp) * QP + kk + thr + 4];
                mma_tf32(s[nt][0], s[nt][1], s[nt][2], s[nt][3],
                         a0, a1, a2, a3, b0, b1);
            }
        }

        // ---- online softmax ----
        float mt0 = -1e30f, mt1 = -1e30f;
#pragma unroll
        for (int nt = 0; nt < 8; nt++) {
#pragma unroll
            for (int i = 0; i < 4; i++) s[nt][i] *= scale;
            mt0 = fmaxf(mt0, fmaxf(s[nt][0], s[nt][1]));
            mt1 = fmaxf(mt1, fmaxf(s[nt][2], s[nt][3]));
        }
        mt0 = fmaxf(mt0, __shfl_xor_sync(0xffffffffu, mt0, 1));
        mt0 = fmaxf(mt0, __shfl_xor_sync(0xffffffffu, mt0, 2));
        mt1 = fmaxf(mt1, __shfl_xor_sync(0xffffffffu, mt1, 1));
        mt1 = fmaxf(mt1, __shfl_xor_sync(0xffffffffu, mt1, 2));

        float mn0 = fmaxf(m0, mt0), mn1 = fmaxf(m1, mt1);
        float al0 = __expf(m0 - mn0), al1 = __expf(m1 - mn1);
        float ls0 = 0.f, ls1 = 0.f;

#pragma unroll
        for (int nt = 0; nt < 8; nt++) {
            float p0 = __expf(s[nt][0] - mn0);
            float p1 = __expf(s[nt][1] - mn0);
            float p2 = __expf(s[nt][2] - mn1);
            float p3 = __expf(s[nt][3] - mn1);
            ls0 += p0 + p1;
            ls1 += p2 + p3;
            uint2* w0 = (uint2*)&sP[(wr + grp    ) * VP + nt * 8 + thr * 2];
            uint2* w1 = (uint2*)&sP[(wr + grp + 8) * VP + nt * 8 + thr * 2];
            *w0 = make_uint2(f2tf32(p0), f2tf32(p1));
            *w1 = make_uint2(f2tf32(p2), f2tf32(p3));
        }
        ls0 += __shfl_xor_sync(0xffffffffu, ls0, 1);
        ls0 += __shfl_xor_sync(0xffffffffu, ls0, 2);
        ls1 += __shfl_xor_sync(0xffffffffu, ls1, 1);
        ls1 += __shfl_xor_sync(0xffffffffu, ls1, 2);

        l0 = l0 * al0 + ls0;  m0 = mn0;
        l1 = l1 * al1 + ls1;  m1 = mn1;
#pragma unroll
        for (int nt = 0; nt < 12; nt++) {
            o[nt][0] *= al0; o[nt][1] *= al0;
            o[nt][2] *= al1; o[nt][3] *= al1;
        }
        __syncwarp();

        // ---- O += P V ----
#pragma unroll
        for (int ks = 0; ks < 8; ks++) {
            const int kk = ks * 8;
            uint32_t a0 = sP[(wr + grp    ) * VP + kk + thr    ];
            uint32_t a1 = sP[(wr + grp + 8) * VP + kk + thr    ];
            uint32_t a2 = sP[(wr + grp    ) * VP + kk + thr + 4];
            uint32_t a3 = sP[(wr + grp + 8) * VP + kk + thr + 4];
#pragma unroll
            for (int nt = 0; nt < 12; nt++) {
                uint32_t b0 = sVT[(nt * 8 + grp) * VP + kk + thr    ];
                uint32_t b1 = sVT[(nt * 8 + grp) * VP + kk + thr + 4];
                mma_tf32(o[nt][0], o[nt][1], o[nt][2], o[nt][3],
                         a0, a1, a2, a3, b0, b1);
            }
        }
    }

    // epilogue: normalize + tf32-round (feeds cvt-free Wo GEMM)
    float inv0 = 1.f / l0, inv1 = 1.f / l1;
    size_t row0 = ((size_t)b * SEQL + q0 + wr + grp    ) * DIMS + h * HD;
    size_t row1 = ((size_t)b * SEQL + q0 + wr + grp + 8) * DIMS + h * HD;
#pragma unroll
    for (int nt = 0; nt < 12; nt++) {
        int c = nt * 8 + thr * 2;
        *(float2*)(O + row0 + c) = make_float2(
            __uint_as_float(f2tf32(o[nt][0] * inv0)),
            __uint_as_float(f2tf32(o[nt][1] * inv0)));
        *(float2*)(O + row1 + c) = make_float2(
            __uint_as_float(f2tf32(o[nt][2] * inv1)),
            __uint_as_float(f2tf32(o[nt][3] * inv1)));
    }
}

// ---------------------------------------------------------------------------
// Launch
// ---------------------------------------------------------------------------
extern "C" void kernel_launch(void* const* d_in, const int* in_sizes, int n_in,
                              void* d_out, int out_size)
{
    const float* Q_in = (const float*)d_in[0];
    const float* K_in = (const float*)d_in[1];
    const float* V_in = (const float*)d_in[2];
    const float* cq   = (const float*)d_in[3];
    const float* ck   = (const float*)d_in[4];
    const float* Wq   = (const float*)d_in[5];
    const float* Wk   = (const float*)d_in[6];
    const float* Wv   = (const float*)d_in[7];
    const float* Wo   = (const float*)d_in[8];
    float* out = (float*)d_out;

    float *q, *k, *v, *att, *wq, *wk, *wv, *wo;
    uint32_t* vt;
    cudaGetSymbolAddress((void**)&q,   g_q);
    cudaGetSymbolAddress((void**)&k,   g_k);
    cudaGetSymbolAddress((void**)&v,   g_v);
    cudaGetSymbolAddress((void**)&att, g_att);
    cudaGetSymbolAddress((void**)&vt,  g_vt);
    cudaGetSymbolAddress((void**)&wq,  g_wq);
    cudaGetSymbolAddress((void**)&wk,  g_wk);
    cudaGetSymbolAddress((void**)&wv,  g_wv);
    cudaGetSymbolAddress((void**)&wo,  g_wo);

    cudaFuncSetAttribute(gemm_qkv_kernel, cudaFuncAttributeMaxDynamicSharedMemorySize,
                         GEMM_SMEM_BYTES);
    cudaFuncSetAttribute(gemm_wo_kernel, cudaFuncAttributeMaxDynamicSharedMemorySize,
                         GEMM_SMEM_BYTES);
    cudaFuncSetAttribute(attn_mma_kernel, cudaFuncAttributeMaxDynamicSharedMemorySize,
                         ATTN_SMEM_BYTES);

    // weights -> tf32 (tiny)
    round_weights_kernel<<<dim3(DIMS * DIMS / 4 / 256, 4), 256>>>(
        Wq, Wk, Wv, Wo, wq, wk, wv, wo);

    // fused Q/K/V projections (A cvt in-loop)
    gemm_qkv_kernel<<<dim3(NROWS / TM, DIMS / TN, 3), 256, GEMM_SMEM_BYTES>>>(
        Q_in, K_in, V_in, wq, wk, wv, q, k, v);

    // fused rope(q) + rope(k) + transpose(v)
    pointwise_kernel<<<dim3(ROPE_BLOCKS, 3), 256>>>(q, cq, k, ck, v, vt);

    // tensor-core flash attention (2 CTAs/SM)
    attn_mma_kernel<<<dim3(SEQL / BQ, HEADS, BATCH), 128, ATTN_SMEM_BYTES>>>(q, k, vt, att);

    // output projection (cvt-free)
    gemm_wo_kernel<<<dim3(NROWS / TM, DIMS / TN), 256, GEMM_SMEM_BYTES>>>(att, wo, out);
}